// round 1
// baseline (speedup 1.0000x reference)
#include <cuda_runtime.h>
#include <cuda_bf16.h>

// SignAdaptor: fused repeat/gather/concat/pad.
//   out[b, j, 0:1024]    = image_batch[foff[b] + j]                (j < nf[b])
//   out[b, j, 1024:2048] = clip_batch [coff[b] + min(j/rf, nc-1)]  (j < nf[b])
//   out[b, j, :]         = pad_idx                                 (j >= nf[b])
//   src_length[b]        = nf[b]   (appended after x if out_size includes it)
//
// Purely HBM-bound: ~150MB stores + ~70MB loads. One CTA per output row,
// 256 threads, one float4 per thread per half-row (512 float4 per row).

#define B_CONST 32
#define D_HALF_VEC 256   // 1024 floats = 256 float4

__device__ int g_foff[B_CONST];
__device__ int g_coff[B_CONST];

// One warp: exclusive prefix sums of nf/nc; optionally write src_length tail.
__global__ void prep_kernel(const int* __restrict__ nf,
                            const int* __restrict__ nc,
                            float* __restrict__ out,
                            long long src_off, int has_src) {
    int b = threadIdx.x;           // 0..31
    int f = nf[b];
    int c = nc[b];
    int fs = f, cs = c;
    #pragma unroll
    for (int o = 1; o < 32; o <<= 1) {
        int vf = __shfl_up_sync(0xffffffffu, fs, o);
        int vc = __shfl_up_sync(0xffffffffu, cs, o);
        if (b >= o) { fs += vf; cs += vc; }
    }
    g_foff[b] = fs - f;   // exclusive scan
    g_coff[b] = cs - c;
    if (has_src) out[src_off + b] = (float)f;
}

__global__ __launch_bounds__(256)
void gather_kernel(const float* __restrict__ img,
                   const float* __restrict__ clip,
                   const int* __restrict__ nf,
                   const int* __restrict__ nc,
                   const int* __restrict__ pad,   // may be null -> 0
                   float* __restrict__ out,
                   int L) {
    const int j = blockIdx.x;          // frame position within padded length
    const int b = blockIdx.y;          // batch
    const int t = threadIdx.x;         // 0..255

    const int n = nf[b];
    float4* __restrict__ orow =
        (float4*)(out + ((long long)(b * L + j)) * 2048);

    if (j < n) {
        const int c   = nc[b];
        const int rf  = n / c;
        int cidx = j / rf;
        const int cmax = c - 1;
        if (cidx > cmax) cidx = cmax;

        const float4* __restrict__ isrc =
            (const float4*)(img + ((long long)(g_foff[b] + j)) * 1024);
        const float4* __restrict__ csrc =
            (const float4*)(clip + ((long long)(g_coff[b] + cidx)) * 1024);

        orow[t]              = isrc[t];
        orow[D_HALF_VEC + t] = csrc[t];
    } else {
        const float pv = pad ? (float)pad[0] : 0.0f;
        const float4 p4 = make_float4(pv, pv, pv, pv);
        orow[t]              = p4;
        orow[D_HALF_VEC + t] = p4;
    }
}

extern "C" void kernel_launch(void* const* d_in, const int* in_sizes, int n_in,
                              void* d_out, int out_size) {
    const float* img  = (const float*)d_in[0];   // image_batch [tf, 1024]
    // d_in[1] = emo_batch (unused by reference)
    const float* clip = (const float*)d_in[2];   // clip_batch  [tc, 1024]
    const int*   nf   = (const int*)d_in[3];     // [32]
    const int*   nc   = (const int*)d_in[4];     // [32]
    const int*   pad  = (n_in >= 6) ? (const int*)d_in[5] : nullptr;

    float* out = (float*)d_out;

    // out_size = B*L*2048 (+ B if src_length is part of the flattened output)
    const long long per = (long long)B_CONST * 2048;
    long long L;
    int has_src;
    if ((long long)out_size % per == 0) {
        L = (long long)out_size / per;
        has_src = 0;
    } else {
        L = ((long long)out_size - B_CONST) / per;
        has_src = 1;
    }

    prep_kernel<<<1, 32>>>(nf, nc, out, (long long)B_CONST * L * 2048, has_src);

    dim3 grid((unsigned)L, B_CONST);
    gather_kernel<<<grid, 256>>>(img, clip, nf, nc, pad, out, (int)L);
}

// round 2
// speedup vs baseline: 1.0557x; 1.0557x over previous
#include <cuda_runtime.h>
#include <cuda_bf16.h>

// SignAdaptor: fused repeat/gather/concat/pad — SINGLE kernel.
//   out[b, j, 0:1024]    = image_batch[foff[b] + j]                (j < nf[b])
//   out[b, j, 1024:2048] = clip_batch [coff[b] + min(j/rf, nc-1)]  (j < nf[b])
//   out[b, j, :]         = pad_idx                                 (j >= nf[b])
//   src_length[b]        = nf[b]   (appended after x when out_size includes it)
//
// HBM-bound (~220 MB traffic). One CTA per output row, 256 threads,
// one float4 per thread per half-row. The per-sample prefix offsets
// (foff/coff) are recomputed redundantly by EVERY warp via a 32-lane
// register scan (2 coalesced LDG + 10 SHFL, no bar.sync, no smem) —
// cheap, latency fully hidden by resident-CTA overlap, and it removes
// the separate prep launch from the graph.

#define B_CONST 32
#define D_HALF_VEC 256   // 1024 floats = 256 float4

__global__ __launch_bounds__(256)
void gather_fused_kernel(const float* __restrict__ img,
                         const float* __restrict__ clip,
                         const int* __restrict__ nf,
                         const int* __restrict__ nc,
                         const int* __restrict__ pad,   // may be null -> 0
                         float* __restrict__ out,
                         int L, long long src_off, int has_src) {
    const int j = blockIdx.x;          // frame position within padded length
    const int b = blockIdx.y;          // batch
    const int t = threadIdx.x;         // 0..255
    const int lane = t & 31;

    // ---- per-warp redundant exclusive scan of nf/nc over B=32 ----
    int f = nf[lane];
    int c = nc[lane];
    int fs = f, cs = c;
    #pragma unroll
    for (int o = 1; o < 32; o <<= 1) {
        int vf = __shfl_up_sync(0xffffffffu, fs, o);
        int vc = __shfl_up_sync(0xffffffffu, cs, o);
        if (lane >= o) { fs += vf; cs += vc; }
    }
    // exclusive offsets for this CTA's batch index b
    const int foff_b = __shfl_sync(0xffffffffu, fs - f, b);
    const int coff_b = __shfl_sync(0xffffffffu, cs - c, b);
    const int n      = __shfl_sync(0xffffffffu, f, b);
    const int cnum   = __shfl_sync(0xffffffffu, c, b);

    float4* __restrict__ orow =
        (float4*)(out + ((long long)(b * L + j)) * 2048);

    if (j < n) {
        const int rf = n / cnum;
        int cidx = j / rf;
        const int cmax = cnum - 1;
        if (cidx > cmax) cidx = cmax;

        const float4* __restrict__ isrc =
            (const float4*)(img + ((long long)(foff_b + j)) * 1024);
        const float4* __restrict__ csrc =
            (const float4*)(clip + ((long long)(coff_b + cidx)) * 1024);

        // image: read-once -> streaming load; clip: 4x reuse -> default (L2).
        const float4 iv = __ldcs(isrc + t);
        const float4 cv = __ldg(csrc + t);
        __stcs(orow + t, iv);                    // write-once -> evict-first
        __stcs(orow + D_HALF_VEC + t, cv);
    } else {
        const float pv = pad ? (float)pad[0] : 0.0f;
        const float4 p4 = make_float4(pv, pv, pv, pv);
        __stcs(orow + t, p4);
        __stcs(orow + D_HALF_VEC + t, p4);
    }

    // src_length tail: one thread per batch row (j==0 blocks).
    if (has_src && j == 0 && t == 0) {
        out[src_off + b] = (float)n;
    }
}

extern "C" void kernel_launch(void* const* d_in, const int* in_sizes, int n_in,
                              void* d_out, int out_size) {
    const float* img  = (const float*)d_in[0];   // image_batch [tf, 1024]
    // d_in[1] = emo_batch (unused by reference)
    const float* clip = (const float*)d_in[2];   // clip_batch  [tc, 1024]
    const int*   nf   = (const int*)d_in[3];     // [32]
    const int*   nc   = (const int*)d_in[4];     // [32]
    const int*   pad  = (n_in >= 6) ? (const int*)d_in[5] : nullptr;

    float* out = (float*)d_out;

    // out_size = B*L*2048 (+ B if src_length is part of the flattened output)
    const long long per = (long long)B_CONST * 2048;
    long long L;
    int has_src;
    if ((long long)out_size % per == 0) {
        L = (long long)out_size / per;
        has_src = 0;
    } else {
        L = ((long long)out_size - B_CONST) / per;
        has_src = 1;
    }

    dim3 grid((unsigned)L, B_CONST);
    gather_fused_kernel<<<grid, 256>>>(img, clip, nf, nc, pad, out,
                                       (int)L, (long long)B_CONST * L * 2048,
                                       has_src);
}